// round 1
// baseline (speedup 1.0000x reference)
#include <cuda_runtime.h>
#include <cuda_bf16.h>
#include <cstdint>
#include <cstddef>

// ---------------------------------------------------------------------------
// Problem constants
// ---------------------------------------------------------------------------
#define BB 4
#define MM 2048
#define DD 1024
#define HH 16
#define DH 64
#define RR 256
#define FD 2048
#define R1 512
#define R2 512
#define BM (BB*MM)          // 8192 rows

// ---------------------------------------------------------------------------
// Scratch (device globals; no allocation allowed)
// ---------------------------------------------------------------------------
__device__ float g_xn  [BM*DD];
__device__ float g_Pq  [BM*RR];
__device__ float g_Pk  [BM*RR];
__device__ float g_Pv  [BM*RR];
__device__ float g_Q   [BM*DD];
__device__ float g_K   [BM*DD];
__device__ float g_V   [BM*DD];
__device__ float g_att [BM*DD];
__device__ float g_xmid[BM*DD];
__device__ float g_xn2 [BM*DD];
__device__ float g_P1  [BM*R1];
__device__ float g_h   [BM*2*FD];
__device__ float g_g   [BM*FD];
__device__ float g_t   [BM*R2];

// ---------------------------------------------------------------------------
// LayerNorm: one block per row of 1024, two-pass (matches reference exactly)
// ---------------------------------------------------------------------------
__global__ void ln_kernel(const float* __restrict__ x, const float* __restrict__ w,
                          const float* __restrict__ b, float* __restrict__ y) {
    __shared__ float red[8];
    __shared__ float red2[8];
    int row = blockIdx.x;
    const float* xr = x + (size_t)row * DD;
    float* yr = y + (size_t)row * DD;
    int t = threadIdx.x;
    float v[4]; float s = 0.f;
#pragma unroll
    for (int i = 0; i < 4; i++) { v[i] = xr[t + 256*i]; s += v[i]; }
#pragma unroll
    for (int o = 16; o; o >>= 1) s += __shfl_xor_sync(0xffffffffu, s, o);
    if ((t & 31) == 0) red[t >> 5] = s;
    __syncthreads();
    float tot = 0.f;
#pragma unroll
    for (int i = 0; i < 8; i++) tot += red[i];
    float mu = tot * (1.f/1024.f);
    float q = 0.f;
#pragma unroll
    for (int i = 0; i < 4; i++) { float d = v[i]-mu; q += d*d; }
#pragma unroll
    for (int o = 16; o; o >>= 1) q += __shfl_xor_sync(0xffffffffu, q, o);
    if ((t & 31) == 0) red2[t >> 5] = q;
    __syncthreads();
    float qt = 0.f;
#pragma unroll
    for (int i = 0; i < 8; i++) qt += red2[i];
    float rstd = rsqrtf(qt * (1.f/1024.f) + 1e-5f);
#pragma unroll
    for (int i = 0; i < 4; i++) {
        int c = t + 256*i;
        yr[c] = (v[i]-mu)*rstd*w[c] + b[c];
    }
}

// ---------------------------------------------------------------------------
// Tiled SGEMM: C[M,N] = A[M,K] @ B (+bias +resid).
// BT=0: B row-major [K,N].  BT=1: B row-major [N,K]  (C = A @ B^T).
// 64x64 tile, BK=16, 256 threads, 4x4 micro-tile.
// All dims assumed multiples of 64 (M) / 64 (N) / 16 (K) -- true here.
// ---------------------------------------------------------------------------
template<int BT>
__global__ void gemm64(const float* __restrict__ A, const float* __restrict__ B,
                       const float* __restrict__ bias, const float* __restrict__ resid,
                       float* __restrict__ C, int M, int N, int K) {
    __shared__ float As[16][64];
    __shared__ float Bs[16][64];
    int tid = threadIdx.x;
    int tx = tid & 15, ty = tid >> 4;
    int m0 = blockIdx.y * 64;
    int n0 = blockIdx.x * 64;
    float acc[4][4];
#pragma unroll
    for (int i = 0; i < 4; i++)
#pragma unroll
        for (int j = 0; j < 4; j++) acc[i][j] = 0.f;

    for (int k0 = 0; k0 < K; k0 += 16) {
        {   // A tile: 64 rows x 16 k, stored transposed As[k][m]
            int ar = tid >> 2;
            int ac = (tid & 3) << 2;
            float4 v = *(const float4*)(A + (size_t)(m0+ar)*K + k0 + ac);
            As[ac+0][ar] = v.x; As[ac+1][ar] = v.y; As[ac+2][ar] = v.z; As[ac+3][ar] = v.w;
        }
        if (BT == 0) {
            int br = tid >> 4;
            int bc = (tid & 15) << 2;
            *(float4*)&Bs[br][bc] = *(const float4*)(B + (size_t)(k0+br)*N + n0 + bc);
        } else {
            int nr = tid >> 2;
            int kc = (tid & 3) << 2;
            float4 v = *(const float4*)(B + (size_t)(n0+nr)*K + k0 + kc);
            Bs[kc+0][nr] = v.x; Bs[kc+1][nr] = v.y; Bs[kc+2][nr] = v.z; Bs[kc+3][nr] = v.w;
        }
        __syncthreads();
#pragma unroll
        for (int kk = 0; kk < 16; kk++) {
            float4 a = *(const float4*)&As[kk][ty*4];
            float4 b4 = *(const float4*)&Bs[kk][tx*4];
            float av[4] = {a.x, a.y, a.z, a.w};
            float bv[4] = {b4.x, b4.y, b4.z, b4.w};
#pragma unroll
            for (int i = 0; i < 4; i++)
#pragma unroll
                for (int j = 0; j < 4; j++) acc[i][j] += av[i]*bv[j];
        }
        __syncthreads();
    }
#pragma unroll
    for (int i = 0; i < 4; i++) {
        int m = m0 + ty*4 + i;
#pragma unroll
        for (int j = 0; j < 4; j++) {
            int n = n0 + tx*4 + j;
            float c = acc[i][j];
            if (bias)  c += bias[n];
            if (resid) c += resid[(size_t)m*N + n];
            C[(size_t)m*N + n] = c;
        }
    }
}

// ---------------------------------------------------------------------------
// RoPE applied in-place to Q and K ([B,M,H,DH] layout). One thread per (b,m,h,j) pair.
// ---------------------------------------------------------------------------
__global__ void rope_kernel(float* __restrict__ Q, float* __restrict__ K) {
    int t = blockIdx.x * blockDim.x + threadIdx.x;
    if (t >= BB*MM*HH*32) return;
    int j  = t & 31;
    int bm = t >> 9;              // (b*M+m)
    int m  = bm & (MM-1);
    float inv = powf(10000.0f, -(float)j * (1.0f/32.0f));
    float ang = (float)m * inv;
    float cs = cosf(ang), sn = sinf(ang);
    size_t base = ((size_t)(t >> 5)) * 64 + j;   // ((b*M+m)*H+h)*64 + j
    float q1 = Q[base], q2 = Q[base+32];
    Q[base]    = q1*cs - q2*sn;
    Q[base+32] = q2*cs + q1*sn;
    float k1 = K[base], k2 = K[base+32];
    K[base]    = k1*cs - k2*sn;
    K[base+32] = k2*cs + k1*sn;
}

// ---------------------------------------------------------------------------
// Flash attention (fp32). Block = (b, h, 64-query tile), 256 threads.
// Both the score GEMM (64x64x64) and the PV GEMM (64x64x64) are register-tiled
// 4x4 per thread so we stay FMA-bound, not LDS-bound.
// Dynamic smem: 4 arrays of 64x68 floats = 69,632 B.
// ---------------------------------------------------------------------------
#define FA_STRIDE 68
#define FA_SMEM (4*64*FA_STRIDE*4)

__global__ void flash_attn(const float* __restrict__ Qg, const float* __restrict__ Kg,
                           const float* __restrict__ Vg, const int* __restrict__ mask,
                           float* __restrict__ Og) {
    extern __shared__ float smem[];
    float (*QT)[FA_STRIDE] = (float(*)[FA_STRIDE])(smem);                   // [d][q]
    float (*KT)[FA_STRIDE] = (float(*)[FA_STRIDE])(smem + 64*FA_STRIDE);    // [d][k]
    float (*Vs)[FA_STRIDE] = (float(*)[FA_STRIDE])(smem + 2*64*FA_STRIDE);  // [k][d]
    float (*SP)[FA_STRIDE] = (float(*)[FA_STRIDE])(smem + 3*64*FA_STRIDE);  // [q][k]

    int b = blockIdx.z, h = blockIdx.y;
    int q0 = blockIdx.x * 64;
    int tid = threadIdx.x;
    int tx = tid & 15, ty = tid >> 4;
    int lr = tid >> 2;
    int lc = (tid & 3) * 16;

    {   // load Q tile transposed
        const float* src = Qg + ((size_t)((b*MM + q0 + lr)*HH + h))*64 + lc;
#pragma unroll
        for (int w = 0; w < 16; w += 4) {
            float4 v = *(const float4*)(src + w);
            QT[lc+w+0][lr] = v.x; QT[lc+w+1][lr] = v.y;
            QT[lc+w+2][lr] = v.z; QT[lc+w+3][lr] = v.w;
        }
    }

    float m_i[4], l_i[4], o[4][4];
#pragma unroll
    for (int i = 0; i < 4; i++) {
        m_i[i] = -3.402823466e38f; l_i[i] = 0.f;
#pragma unroll
        for (int j = 0; j < 4; j++) o[i][j] = 0.f;
    }

    for (int k0 = 0; k0 < MM; k0 += 64) {
        __syncthreads();
        {   // load K (transposed) and V (natural)
            size_t base = ((size_t)((b*MM + k0 + lr)*HH + h))*64 + lc;
#pragma unroll
            for (int w = 0; w < 16; w += 4) {
                float4 kv = *(const float4*)(Kg + base + w);
                KT[lc+w+0][lr] = kv.x; KT[lc+w+1][lr] = kv.y;
                KT[lc+w+2][lr] = kv.z; KT[lc+w+3][lr] = kv.w;
                float4 vv = *(const float4*)(Vg + base + w);
                *(float4*)&Vs[lr][lc+w] = vv;
            }
        }
        __syncthreads();

        // ---- score GEMM: S[q,k] = sum_d Q[q,d]*K[k,d]
        float s[4][4];
#pragma unroll
        for (int i = 0; i < 4; i++)
#pragma unroll
            for (int j = 0; j < 4; j++) s[i][j] = 0.f;
#pragma unroll
        for (int d = 0; d < 64; d++) {
            float4 a  = *(const float4*)&QT[d][ty*4];
            float4 b4 = *(const float4*)&KT[d][tx*4];
            float av[4] = {a.x, a.y, a.z, a.w};
            float bv[4] = {b4.x, b4.y, b4.z, b4.w};
#pragma unroll
            for (int i = 0; i < 4; i++)
#pragma unroll
                for (int j = 0; j < 4; j++) s[i][j] += av[i]*bv[j];
        }

        // ---- scale + mask
        int mk[4];
#pragma unroll
        for (int j = 0; j < 4; j++) mk[j] = mask[b*MM + k0 + tx*4 + j];
#pragma unroll
        for (int i = 0; i < 4; i++)
#pragma unroll
            for (int j = 0; j < 4; j++) {
                float v = s[i][j] * 0.125f;
                s[i][j] = (mk[j] == 0) ? -3.402823466e38f : v;
            }

        // ---- online softmax (row reductions across the 16 tx lanes)
#pragma unroll
        for (int i = 0; i < 4; i++) {
            float mx = fmaxf(fmaxf(s[i][0], s[i][1]), fmaxf(s[i][2], s[i][3]));
#pragma unroll
            for (int off = 1; off < 16; off <<= 1)
                mx = fmaxf(mx, __shfl_xor_sync(0xffffffffu, mx, off));
            float mnew = fmaxf(m_i[i], mx);
            float corr = expf(m_i[i] - mnew);
            float lsum = 0.f;
#pragma unroll
            for (int j = 0; j < 4; j++) {
                float p = expf(s[i][j] - mnew);
                lsum += p;
                s[i][j] = p;
            }
#pragma unroll
            for (int off = 1; off < 16; off <<= 1)
                lsum += __shfl_xor_sync(0xffffffffu, lsum, off);
            l_i[i] = l_i[i]*corr + lsum;
            m_i[i] = mnew;
#pragma unroll
            for (int j = 0; j < 4; j++) o[i][j] *= corr;
            // stash p tile
            *(float4*)&SP[ty*4+i][tx*4] = make_float4(s[i][0], s[i][1], s[i][2], s[i][3]);
        }
        __syncwarp();   // SP rows are produced/consumed within one warp's 16-lane group

        // ---- PV GEMM: O[q,d] += sum_k P[q,k]*V[k,d]
#pragma unroll
        for (int kk = 0; kk < 64; kk++) {
            float a0 = SP[ty*4+0][kk];
            float a1 = SP[ty*4+1][kk];
            float a2 = SP[ty*4+2][kk];
            float a3 = SP[ty*4+3][kk];
            float4 bv = *(const float4*)&Vs[kk][tx*4];
            o[0][0] += a0*bv.x; o[0][1] += a0*bv.y; o[0][2] += a0*bv.z; o[0][3] += a0*bv.w;
            o[1][0] += a1*bv.x; o[1][1] += a1*bv.y; o[1][2] += a1*bv.z; o[1][3] += a1*bv.w;
            o[2][0] += a2*bv.x; o[2][1] += a2*bv.y; o[2][2] += a2*bv.z; o[2][3] += a2*bv.w;
            o[3][0] += a3*bv.x; o[3][1] += a3*bv.y; o[3][2] += a3*bv.z; o[3][3] += a3*bv.w;
        }
    }

#pragma unroll
    for (int i = 0; i < 4; i++) {
        float inv = 1.f / l_i[i];
        size_t base = ((size_t)((b*MM + q0 + ty*4 + i)*HH + h))*64 + tx*4;
        float4 r = make_float4(o[i][0]*inv, o[i][1]*inv, o[i][2]*inv, o[i][3]*inv);
        *(float4*)(Og + base) = r;
    }
}

// ---------------------------------------------------------------------------
// GEGLU: g = gelu_tanh(h1) * h2
// ---------------------------------------------------------------------------
__global__ void geglu_kernel(const float* __restrict__ h, float* __restrict__ g) {
    int idx = blockIdx.x * blockDim.x + threadIdx.x;
    if (idx >= BM*FD) return;
    int row = idx >> 11;          // FD = 2048
    int col = idx & (FD-1);
    float a  = h[(size_t)row*(2*FD) + col];
    float b2 = h[(size_t)row*(2*FD) + FD + col];
    float inner = 0.7978845608028654f * (a + 0.044715f*a*a*a);
    float gg = 0.5f*a*(1.f + tanhf(inner));
    g[idx] = gg * b2;
}

// ---------------------------------------------------------------------------
// Launch
// ---------------------------------------------------------------------------
extern "C" void kernel_launch(void* const* d_in, const int* in_sizes, int n_in,
                              void* d_out, int out_size) {
    const float* x    = (const float*)d_in[0];
    const int*   mask = (const int*)  d_in[1];
    const float* ln1w = (const float*)d_in[2];
    const float* ln1b = (const float*)d_in[3];
    const float* ln2w = (const float*)d_in[4];
    const float* ln2b = (const float*)d_in[5];
    const float* Uq   = (const float*)d_in[6];
    const float* Uk   = (const float*)d_in[7];
    const float* Uv   = (const float*)d_in[8];
    const float* Vq   = (const float*)d_in[9];
    const float* Vk   = (const float*)d_in[10];
    const float* Vv   = (const float*)d_in[11];
    const float* bq   = (const float*)d_in[12];
    const float* bk   = (const float*)d_in[13];
    const float* bv   = (const float*)d_in[14];
    const float* Wo_w = (const float*)d_in[15];
    const float* Wo_b = (const float*)d_in[16];
    const float* U1   = (const float*)d_in[17];
    const float* V1   = (const float*)d_in[18];
    const float* b1   = (const float*)d_in[19];
    const float* U2   = (const float*)d_in[20];
    const float* V2   = (const float*)d_in[21];
    const float* b2   = (const float*)d_in[22];
    float* out = (float*)d_out;

    float *xn, *Pq, *Pk, *Pv, *Qb, *Kb, *Vb, *att, *xmid, *xn2, *P1, *hb, *gb, *tb;
    cudaGetSymbolAddress((void**)&xn,   g_xn);
    cudaGetSymbolAddress((void**)&Pq,   g_Pq);
    cudaGetSymbolAddress((void**)&Pk,   g_Pk);
    cudaGetSymbolAddress((void**)&Pv,   g_Pv);
    cudaGetSymbolAddress((void**)&Qb,   g_Q);
    cudaGetSymbolAddress((void**)&Kb,   g_K);
    cudaGetSymbolAddress((void**)&Vb,   g_V);
    cudaGetSymbolAddress((void**)&att,  g_att);
    cudaGetSymbolAddress((void**)&xmid, g_xmid);
    cudaGetSymbolAddress((void**)&xn2,  g_xn2);
    cudaGetSymbolAddress((void**)&P1,   g_P1);
    cudaGetSymbolAddress((void**)&hb,   g_h);
    cudaGetSymbolAddress((void**)&gb,   g_g);
    cudaGetSymbolAddress((void**)&tb,   g_t);

    // LN1
    ln_kernel<<<BM, 256>>>(x, ln1w, ln1b, xn);

    // rank-space projections: P = xn @ U  [8192 x 256], K=1024
    gemm64<0><<<dim3(RR/64, BM/64), 256>>>(xn, Uq, nullptr, nullptr, Pq, BM, RR, DD);
    gemm64<0><<<dim3(RR/64, BM/64), 256>>>(xn, Uk, nullptr, nullptr, Pk, BM, RR, DD);
    gemm64<0><<<dim3(RR/64, BM/64), 256>>>(xn, Uv, nullptr, nullptr, Pv, BM, RR, DD);

    // expand: Q = P @ V + b  [8192 x 1024], K=256
    gemm64<0><<<dim3(DD/64, BM/64), 256>>>(Pq, Vq, bq, nullptr, Qb, BM, DD, RR);
    gemm64<0><<<dim3(DD/64, BM/64), 256>>>(Pk, Vk, bk, nullptr, Kb, BM, DD, RR);
    gemm64<0><<<dim3(DD/64, BM/64), 256>>>(Pv, Vv, bv, nullptr, Vb, BM, DD, RR);

    // RoPE on Q, K
    rope_kernel<<<(BB*MM*HH*32)/256, 256>>>(Qb, Kb);

    // flash attention
    cudaFuncSetAttribute(flash_attn, cudaFuncAttributeMaxDynamicSharedMemorySize, FA_SMEM);
    flash_attn<<<dim3(MM/64, HH, BB), 256, FA_SMEM>>>(Qb, Kb, Vb, mask, att);

    // Wo projection (+bias, +residual x) -> xmid
    gemm64<1><<<dim3(DD/64, BM/64), 256>>>(att, Wo_w, Wo_b, x, xmid, BM, DD, DD);

    // LN2
    ln_kernel<<<BM, 256>>>(xmid, ln2w, ln2b, xn2);

    // FFN: P1 = xn2 @ U1 [8192 x 512], K=1024
    gemm64<0><<<dim3(R1/64, BM/64), 256>>>(xn2, U1, nullptr, nullptr, P1, BM, R1, DD);
    // h = P1 @ V1 + b1 [8192 x 4096], K=512
    gemm64<0><<<dim3((2*FD)/64, BM/64), 256>>>(P1, V1, b1, nullptr, hb, BM, 2*FD, R1);
    // GEGLU
    geglu_kernel<<<(BM*FD)/256, 256>>>(hb, gb);
    // t = g @ U2 [8192 x 512], K=2048
    gemm64<0><<<dim3(R2/64, BM/64), 256>>>(gb, U2, nullptr, nullptr, tb, BM, R2, FD);
    // out = t @ V2 + b2 + xmid [8192 x 1024], K=512
    gemm64<0><<<dim3(DD/64, BM/64), 256>>>(tb, V2, b2, xmid, out, BM, DD, R2);
}

// round 3
// speedup vs baseline: 1.7820x; 1.7820x over previous
#include <cuda_runtime.h>
#include <cuda_bf16.h>
#include <cstdint>
#include <cstddef>

// ---------------------------------------------------------------------------
// Problem constants
// ---------------------------------------------------------------------------
#define BB 4
#define MM 2048
#define DD 1024
#define HH 16
#define DH 64
#define RR 256
#define FD 2048
#define R1 512
#define R2 512
#define BM (BB*MM)          // 8192 rows

// ---------------------------------------------------------------------------
// Scratch (device globals; no allocation allowed)
// ---------------------------------------------------------------------------
__device__ float g_xn  [BM*DD];
__device__ float g_Pq  [BM*RR];
__device__ float g_Pk  [BM*RR];
__device__ float g_Pv  [BM*RR];
__device__ float g_Q   [BM*DD];
__device__ float g_K   [BM*DD];
__device__ float g_V   [BM*DD];
__device__ float g_att [BM*DD];
__device__ float g_xmid[BM*DD];
__device__ float g_xn2 [BM*DD];
__device__ float g_P1  [BM*R1];
__device__ float g_h   [BM*2*FD];
__device__ float g_g   [BM*FD];
__device__ float g_t   [BM*R2];

// rounded (tf32) weights, contiguous scratch
#define OFF_Uq  0
#define OFF_Uk  (OFF_Uq + DD*RR)
#define OFF_Uv  (OFF_Uk + DD*RR)
#define OFF_Vq  (OFF_Uv + DD*RR)
#define OFF_Vk  (OFF_Vq + RR*DD)
#define OFF_Vv  (OFF_Vk + RR*DD)
#define OFF_WoT (OFF_Vv + RR*DD)
#define OFF_U1  (OFF_WoT + DD*DD)
#define OFF_V1  (OFF_U1 + DD*R1)
#define OFF_U2  (OFF_V1 + R1*2*FD)
#define OFF_V2  (OFF_U2 + FD*R2)
#define RW_TOT  (OFF_V2 + R2*DD)
__device__ float g_rw[RW_TOT];

// ---------------------------------------------------------------------------
// tf32 round-to-nearest helper
// ---------------------------------------------------------------------------
__device__ __forceinline__ float tf32r(float x) {
    uint32_t u;
    asm("cvt.rna.tf32.f32 %0, %1;" : "=r"(u) : "f"(x));
    return __uint_as_float(u);
}

// ---------------------------------------------------------------------------
// Weight prep: round-copy and transpose-round
// ---------------------------------------------------------------------------
__global__ void round_copy(const float4* __restrict__ src, float4* __restrict__ dst, int n4) {
    int i = blockIdx.x * blockDim.x + threadIdx.x;
    if (i >= n4) return;
    float4 v = src[i];
    v.x = tf32r(v.x); v.y = tf32r(v.y); v.z = tf32r(v.z); v.w = tf32r(v.w);
    dst[i] = v;
}

// dst[k][n] = round(src[n][k]) for square D x D
__global__ void transpose_round(const float* __restrict__ src, float* __restrict__ dst, int D) {
    __shared__ float t[32][33];
    int x = blockIdx.x * 32 + threadIdx.x;
    int y = blockIdx.y * 32;
#pragma unroll
    for (int j = threadIdx.y; j < 32; j += 8)
        t[j][threadIdx.x] = src[(size_t)(y + j) * D + x];
    __syncthreads();
    int xo = blockIdx.y * 32 + threadIdx.x;
    int yo = blockIdx.x * 32;
#pragma unroll
    for (int j = threadIdx.y; j < 32; j += 8)
        dst[(size_t)(yo + j) * D + xo] = tf32r(t[threadIdx.x][j]);
}

// ---------------------------------------------------------------------------
// LayerNorm: one block per row of 1024; output tf32-rounded (feeds GEMM A only)
// ---------------------------------------------------------------------------
__global__ void ln_kernel(const float* __restrict__ x, const float* __restrict__ w,
                          const float* __restrict__ b, float* __restrict__ y) {
    __shared__ float red[8];
    __shared__ float red2[8];
    int row = blockIdx.x;
    const float* xr = x + (size_t)row * DD;
    float* yr = y + (size_t)row * DD;
    int t = threadIdx.x;
    float v[4]; float s = 0.f;
#pragma unroll
    for (int i = 0; i < 4; i++) { v[i] = xr[t + 256*i]; s += v[i]; }
#pragma unroll
    for (int o = 16; o; o >>= 1) s += __shfl_xor_sync(0xffffffffu, s, o);
    if ((t & 31) == 0) red[t >> 5] = s;
    __syncthreads();
    float tot = 0.f;
#pragma unroll
    for (int i = 0; i < 8; i++) tot += red[i];
    float mu = tot * (1.f/1024.f);
    float q = 0.f;
#pragma unroll
    for (int i = 0; i < 4; i++) { float d = v[i]-mu; q += d*d; }
#pragma unroll
    for (int o = 16; o; o >>= 1) q += __shfl_xor_sync(0xffffffffu, q, o);
    if ((t & 31) == 0) red2[t >> 5] = q;
    __syncthreads();
    float qt = 0.f;
#pragma unroll
    for (int i = 0; i < 8; i++) qt += red2[i];
    float rstd = rsqrtf(qt * (1.f/1024.f) + 1e-5f);
#pragma unroll
    for (int i = 0; i < 4; i++) {
        int c = t + 256*i;
        yr[c] = tf32r((v[i]-mu)*rstd*w[c] + b[c]);
    }
}

// ---------------------------------------------------------------------------
// TF32 tensor-core GEMM. C[M,N] = A[M,K] @ B[K,N] (+bias +resid, opt round).
// Block tile 128x128, BK=16, 256 threads, 8 warps (warp tile 64x32).
// A,B must be tf32-rounded fp32. cp.async double-buffered.
// M % 128 == 0, N % 128 == 0, K % 16 == 0.
// gridDim.z batches independent (A,B,bias,resid,C) tuples.
// ---------------------------------------------------------------------------
struct GemmOp { const float* A; const float* B; const float* bias; const float* resid; float* C; };
struct GemmBatch { GemmOp op[3]; };

__device__ __forceinline__ void mma8(float* c, const uint32_t* a, const uint32_t* b) {
    asm volatile("mma.sync.aligned.m16n8k8.row.col.f32.tf32.tf32.f32 "
                 "{%0,%1,%2,%3}, {%4,%5,%6,%7}, {%8,%9}, {%0,%1,%2,%3};"
                 : "+f"(c[0]), "+f"(c[1]), "+f"(c[2]), "+f"(c[3])
                 : "r"(a[0]), "r"(a[1]), "r"(a[2]), "r"(a[3]), "r"(b[0]), "r"(b[1]));
}

__device__ __forceinline__ void cp16(uint32_t dst, const float* src) {
    asm volatile("cp.async.ca.shared.global [%0], [%1], 16;" :: "r"(dst), "l"(src));
}

#define AS_STRIDE 20
#define BS_STRIDE 136

template<int ROUND_OUT>
__global__ __launch_bounds__(256, 2)
void gemm_tf32(GemmBatch args, int M, int N, int K) {
    __shared__ float As[2*128*AS_STRIDE];
    __shared__ float Bs[2*16*BS_STRIDE];

    const GemmOp op = args.op[blockIdx.z];
    const float* __restrict__ A = op.A;
    const float* __restrict__ B = op.B;

    int tid = threadIdx.x;
    int wid = tid >> 5, lane = tid & 31;
    int lr4 = lane >> 2, lc4 = lane & 3;
    int wm = wid >> 2, wn = wid & 3;       // warp grid 2x4
    int mw = wm * 64, nw = wn * 32;
    int m0 = blockIdx.y * 128;
    int n0 = blockIdx.x * 128;

    uint32_t asB = (uint32_t)__cvta_generic_to_shared(As);
    uint32_t bsB = (uint32_t)__cvta_generic_to_shared(Bs);

    float acc[4][4][4];
#pragma unroll
    for (int i = 0; i < 4; i++)
#pragma unroll
        for (int j = 0; j < 4; j++)
#pragma unroll
            for (int k = 0; k < 4; k++) acc[i][j][k] = 0.f;

    auto load_stage = [&](int buf, int k0) {
        uint32_t ab = asB + buf * (128*AS_STRIDE*4);
        uint32_t bb = bsB + buf * (16*BS_STRIDE*4);
#pragma unroll
        for (int j = 0; j < 2; j++) {      // A: 128 rows x 16k = 512 chunks
            int cc = tid + 256*j;
            int row = cc >> 2, kc = (cc & 3) << 2;
            cp16(ab + (row*AS_STRIDE + kc)*4, A + (size_t)(m0+row)*K + k0 + kc);
        }
#pragma unroll
        for (int j = 0; j < 2; j++) {      // B: 16 rows x 128n = 512 chunks
            int cc = tid + 256*j;
            int row = cc >> 5, nc = (cc & 31) << 2;
            cp16(bb + (row*BS_STRIDE + nc)*4, B + (size_t)(k0+row)*N + n0 + nc);
        }
        asm volatile("cp.async.commit_group;" ::: "memory");
    };

    load_stage(0, 0);
    int nst = K >> 4;
    for (int s = 0; s < nst; s++) {
        if (s + 1 < nst) {
            load_stage((s+1) & 1, (s+1) << 4);
            asm volatile("cp.async.wait_group 1;" ::: "memory");
        } else {
            asm volatile("cp.async.wait_group 0;" ::: "memory");
        }
        __syncthreads();

        const float* Ac = As + (s & 1) * (128*AS_STRIDE);
        const float* Bc = Bs + (s & 1) * (16*BS_STRIDE);
#pragma unroll
        for (int ks = 0; ks < 16; ks += 8) {
            uint32_t af[4][4], bf[4][2];
#pragma unroll
            for (int mi = 0; mi < 4; mi++) {
                int m = mw + mi*16 + lr4;
                af[mi][0] = __float_as_uint(Ac[m*AS_STRIDE + ks + lc4]);
                af[mi][1] = __float_as_uint(Ac[(m+8)*AS_STRIDE + ks + lc4]);
                af[mi][2] = __float_as_uint(Ac[m*AS_STRIDE + ks + lc4 + 4]);
                af[mi][3] = __float_as_uint(Ac[(m+8)*AS_STRIDE + ks + lc4 + 4]);
            }
#pragma unroll
            for (int ni = 0; ni < 4; ni++) {
                int n = nw + ni*8 + lr4;
                bf[ni][0] = __float_as_uint(Bc[(ks + lc4)*BS_STRIDE + n]);
                bf[ni][1] = __float_as_uint(Bc[(ks + lc4 + 4)*BS_STRIDE + n]);
            }
#pragma unroll
            for (int mi = 0; mi < 4; mi++)
#pragma unroll
                for (int ni = 0; ni < 4; ni++)
                    mma8(acc[mi][ni], af[mi], bf[ni]);
        }
        __syncthreads();
    }

    // epilogue
    const float* bias  = op.bias;
    const float* resid = op.resid;
    float* C = op.C;
#pragma unroll
    for (int mi = 0; mi < 4; mi++) {
        int r0 = m0 + mw + mi*16 + lr4;
#pragma unroll
        for (int ni = 0; ni < 4; ni++) {
            int c0 = n0 + nw + ni*8 + lc4*2;
            float v0 = acc[mi][ni][0], v1 = acc[mi][ni][1];
            float v2 = acc[mi][ni][2], v3 = acc[mi][ni][3];
            if (bias) {
                float b0 = bias[c0], b1 = bias[c0+1];
                v0 += b0; v1 += b1; v2 += b0; v3 += b1;
            }
            if (resid) {
                v0 += resid[(size_t)r0*N + c0];
                v1 += resid[(size_t)r0*N + c0 + 1];
                v2 += resid[(size_t)(r0+8)*N + c0];
                v3 += resid[(size_t)(r0+8)*N + c0 + 1];
            }
            if (ROUND_OUT) { v0 = tf32r(v0); v1 = tf32r(v1); v2 = tf32r(v2); v3 = tf32r(v3); }
            *(float2*)&C[(size_t)r0*N + c0]     = make_float2(v0, v1);
            *(float2*)&C[(size_t)(r0+8)*N + c0] = make_float2(v2, v3);
        }
    }
}

// ---------------------------------------------------------------------------
// RoPE applied in-place to Q and K ([B,M,H,DH] layout)
// ---------------------------------------------------------------------------
__global__ void rope_kernel(float* __restrict__ Q, float* __restrict__ K) {
    int t = blockIdx.x * blockDim.x + threadIdx.x;
    if (t >= BB*MM*HH*32) return;
    int j  = t & 31;
    int bm = t >> 9;
    int m  = bm & (MM-1);
    float inv = powf(10000.0f, -(float)j * (1.0f/32.0f));
    float ang = (float)m * inv;
    float cs = cosf(ang), sn = sinf(ang);
    size_t base = ((size_t)(t >> 5)) * 64 + j;
    float q1 = Q[base], q2 = Q[base+32];
    Q[base]    = q1*cs - q2*sn;
    Q[base+32] = q2*cs + q1*sn;
    float k1 = K[base], k2 = K[base+32];
    K[base]    = k1*cs - k2*sn;
    K[base+32] = k2*cs + k1*sn;
}

// ---------------------------------------------------------------------------
// Flash attention (fp32). Output tf32-rounded (feeds Wo GEMM as A operand).
// ---------------------------------------------------------------------------
#define FA_STRIDE 68
#define FA_SMEM (4*64*FA_STRIDE*4)

__global__ void flash_attn(const float* __restrict__ Qg, const float* __restrict__ Kg,
                           const float* __restrict__ Vg, const int* __restrict__ mask,
                           float* __restrict__ Og) {
    extern __shared__ float smem[];
    float (*QT)[FA_STRIDE] = (float(*)[FA_STRIDE])(smem);
    float (*KT)[FA_STRIDE] = (float(*)[FA_STRIDE])(smem + 64*FA_STRIDE);
    float (*Vs)[FA_STRIDE] = (float(*)[FA_STRIDE])(smem + 2*64*FA_STRIDE);
    float (*SP)[FA_STRIDE] = (float(*)[FA_STRIDE])(smem + 3*64*FA_STRIDE);

    int b = blockIdx.z, h = blockIdx.y;
    int q0 = blockIdx.x * 64;
    int tid = threadIdx.x;
    int tx = tid & 15, ty = tid >> 4;
    int lr = tid >> 2;
    int lc = (tid & 3) * 16;

    {
        const float* src = Qg + ((size_t)((b*MM + q0 + lr)*HH + h))*64 + lc;
#pragma unroll
        for (int w = 0; w < 16; w += 4) {
            float4 v = *(const float4*)(src + w);
            QT[lc+w+0][lr] = v.x; QT[lc+w+1][lr] = v.y;
            QT[lc+w+2][lr] = v.z; QT[lc+w+3][lr] = v.w;
        }
    }

    float m_i[4], l_i[4], o[4][4];
#pragma unroll
    for (int i = 0; i < 4; i++) {
        m_i[i] = -3.402823466e38f; l_i[i] = 0.f;
#pragma unroll
        for (int j = 0; j < 4; j++) o[i][j] = 0.f;
    }

    for (int k0 = 0; k0 < MM; k0 += 64) {
        __syncthreads();
        {
            size_t base = ((size_t)((b*MM + k0 + lr)*HH + h))*64 + lc;
#pragma unroll
            for (int w = 0; w < 16; w += 4) {
                float4 kv = *(const float4*)(Kg + base + w);
                KT[lc+w+0][lr] = kv.x; KT[lc+w+1][lr] = kv.y;
                KT[lc+w+2][lr] = kv.z; KT[lc+w+3][lr] = kv.w;
                float4 vv = *(const float4*)(Vg + base + w);
                *(float4*)&Vs[lr][lc+w] = vv;
            }
        }
        __syncthreads();

        float s[4][4];
#pragma unroll
        for (int i = 0; i < 4; i++)
#pragma unroll
            for (int j = 0; j < 4; j++) s[i][j] = 0.f;
#pragma unroll
        for (int d = 0; d < 64; d++) {
            float4 a  = *(const float4*)&QT[d][ty*4];
            float4 b4 = *(const float4*)&KT[d][tx*4];
            float av[4] = {a.x, a.y, a.z, a.w};
            float bv[4] = {b4.x, b4.y, b4.z, b4.w};
#pragma unroll
            for (int i = 0; i < 4; i++)
#pragma unroll
                for (int j = 0; j < 4; j++) s[i][j] += av[i]*bv[j];
        }

        int mk[4];
#pragma unroll
        for (int j = 0; j < 4; j++) mk[j] = mask[b*MM + k0 + tx*4 + j];
#pragma unroll
        for (int i = 0; i < 4; i++)
#pragma unroll
            for (int j = 0; j < 4; j++) {
                float v = s[i][j] * 0.125f;
                s[i][j] = (mk[j] == 0) ? -3.402823466e38f : v;
            }

#pragma unroll
        for (int i = 0; i < 4; i++) {
            float mx = fmaxf(fmaxf(s[i][0], s[i][1]), fmaxf(s[i][2], s[i][3]));
#pragma unroll
            for (int off = 1; off < 16; off <<= 1)
                mx = fmaxf(mx, __shfl_xor_sync(0xffffffffu, mx, off));
            float mnew = fmaxf(m_i[i], mx);
            float corr = expf(m_i[i] - mnew);
            float lsum = 0.f;
#pragma unroll
            for (int j = 0; j < 4; j++) {
                float p = expf(s[i][j] - mnew);
                lsum += p;
                s[i][j] = p;
            }
#pragma unroll
            for (int off = 1; off < 16; off <<= 1)
                lsum += __shfl_xor_sync(0xffffffffu, lsum, off);
            l_i[i] = l_i[i]*corr + lsum;
            m_i[i] = mnew;
#pragma unroll
            for (int j = 0; j < 4; j++) o[i][j] *= corr;
            *(float4*)&SP[ty*4+i][tx*4] = make_float4(s[i][0], s[i][1], s[i][2], s[i][3]);
        }
        __syncwarp();

#pragma unroll
        for (int kk = 0; kk < 64; kk++) {
            float a0 = SP[ty*4+0][kk];
            float a1 = SP[ty*4+1][kk];
            float a2 = SP[ty*4+2][kk];
            float a3 = SP[ty*4+3][kk];
            float4 bv = *(const float4*)&Vs[kk][tx*4];
            o[0][0] += a0*bv.x; o[0][1] += a0*bv.y; o[0][2] += a0*bv.z; o[0][3] += a0*bv.w;
            o[1][0] += a1*bv.x; o[1][1] += a1*bv.y; o[1][2] += a1*bv.z; o[1][3] += a1*bv.w;
            o[2][0] += a2*bv.x; o[2][1] += a2*bv.y; o[2][2] += a2*bv.z; o[2][3] += a2*bv.w;
            o[3][0] += a3*bv.x; o[3][1] += a3*bv.y; o[3][2] += a3*bv.z; o[3][3] += a3*bv.w;
        }
    }

#pragma unroll
    for (int i = 0; i < 4; i++) {
        float inv = 1.f / l_i[i];
        size_t base = ((size_t)((b*MM + q0 + ty*4 + i)*HH + h))*64 + tx*4;
        float4 r = make_float4(tf32r(o[i][0]*inv), tf32r(o[i][1]*inv),
                               tf32r(o[i][2]*inv), tf32r(o[i][3]*inv));
        *(float4*)(Og + base) = r;
    }
}

// ---------------------------------------------------------------------------
// GEGLU: g = gelu_tanh(h1) * h2, tf32-rounded (feeds U2 GEMM as A)
// ---------------------------------------------------------------------------
__global__ void geglu_kernel(const float* __restrict__ h, float* __restrict__ g) {
    int idx = blockIdx.x * blockDim.x + threadIdx.x;
    if (idx >= BM*FD) return;
    int row = idx >> 11;
    int col = idx & (FD-1);
    float a  = h[(size_t)row*(2*FD) + col];
    float b2 = h[(size_t)row*(2*FD) + FD + col];
    float inner = 0.7978845608028654f * (a + 0.044715f*a*a*a);
    float gg = 0.5f*a*(1.f + tanhf(inner));
    g[idx] = tf32r(gg * b2);
}

// ---------------------------------------------------------------------------
// Launch
// ---------------------------------------------------------------------------
extern "C" void kernel_launch(void* const* d_in, const int* in_sizes, int n_in,
                              void* d_out, int out_size) {
    const float* x    = (const float*)d_in[0];
    const int*   mask = (const int*)  d_in[1];
    const float* ln1w = (const float*)d_in[2];
    const float* ln1b = (const float*)d_in[3];
    const float* ln2w = (const float*)d_in[4];
    const float* ln2b = (const float*)d_in[5];
    const float* Uq   = (const float*)d_in[6];
    const float* Uk   = (const float*)d_in[7];
    const float* Uv   = (const float*)d_in[8];
    const float* Vq   = (const float*)d_in[9];
    const float* Vk   = (const float*)d_in[10];
    const float* Vv   = (const float*)d_in[11];
    const float* bq   = (const float*)d_in[12];
    const float* bk   = (const float*)d_in[13];
    const float* bv   = (const float*)d_in[14];
    const float* Wo_w = (const float*)d_in[15];
    const float* Wo_b = (const float*)d_in[16];
    const float* U1   = (const float*)d_in[17];
    const float* V1   = (const float*)d_in[18];
    const float* b1   = (const float*)d_in[19];
    const float* U2   = (const float*)d_in[20];
    const float* V2   = (const float*)d_in[21];
    const float* b2   = (const float*)d_in[22];
    float* out = (float*)d_out;

    float *xn, *Pq, *Pk, *Pv, *Qb, *Kb, *Vb, *att, *xmid, *xn2, *P1, *hb, *gb, *tb, *rw;
    cudaGetSymbolAddress((void**)&xn,   g_xn);
    cudaGetSymbolAddress((void**)&Pq,   g_Pq);
    cudaGetSymbolAddress((void**)&Pk,   g_Pk);
    cudaGetSymbolAddress((void**)&Pv,   g_Pv);
    cudaGetSymbolAddress((void**)&Qb,   g_Q);
    cudaGetSymbolAddress((void**)&Kb,   g_K);
    cudaGetSymbolAddress((void**)&Vb,   g_V);
    cudaGetSymbolAddress((void**)&att,  g_att);
    cudaGetSymbolAddress((void**)&xmid, g_xmid);
    cudaGetSymbolAddress((void**)&xn2,  g_xn2);
    cudaGetSymbolAddress((void**)&P1,   g_P1);
    cudaGetSymbolAddress((void**)&hb,   g_h);
    cudaGetSymbolAddress((void**)&gb,   g_g);
    cudaGetSymbolAddress((void**)&tb,   g_t);
    cudaGetSymbolAddress((void**)&rw,   g_rw);

    // ---- weight prep (tf32 round; Wo transposed) ----
    auto rc = [&](const float* s, float* d, int n) {
        round_copy<<<(n/4 + 255)/256, 256>>>((const float4*)s, (float4*)d, n/4);
    };
    rc(Uq, rw+OFF_Uq, DD*RR);  rc(Uk, rw+OFF_Uk, DD*RR);  rc(Uv, rw+OFF_Uv, DD*RR);
    rc(Vq, rw+OFF_Vq, RR*DD);  rc(Vk, rw+OFF_Vk, RR*DD);  rc(Vv, rw+OFF_Vv, RR*DD);
    rc(U1, rw+OFF_U1, DD*R1);  rc(V1, rw+OFF_V1, R1*2*FD);
    rc(U2, rw+OFF_U2, FD*R2);  rc(V2, rw+OFF_V2, R2*DD);
    transpose_round<<<dim3(DD/32, DD/32), dim3(32,8)>>>(Wo_w, rw+OFF_WoT, DD);

    // ---- LN1 (rounded) ----
    ln_kernel<<<BM, 256>>>(x, ln1w, ln1b, xn);

    // ---- rank-space projections (batched z=3): P = xn @ U, rounded output ----
    {
        GemmBatch a{};
        a.op[0] = {xn, rw+OFF_Uq, nullptr, nullptr, Pq};
        a.op[1] = {xn, rw+OFF_Uk, nullptr, nullptr, Pk};
        a.op[2] = {xn, rw+OFF_Uv, nullptr, nullptr, Pv};
        gemm_tf32<1><<<dim3(RR/128, BM/128, 3), 256>>>(a, BM, RR, DD);
    }
    // ---- expand (batched z=3): Q/K/V = P @ V + b ----
    {
        GemmBatch a{};
        a.op[0] = {Pq, rw+OFF_Vq, bq, nullptr, Qb};
        a.op[1] = {Pk, rw+OFF_Vk, bk, nullptr, Kb};
        a.op[2] = {Pv, rw+OFF_Vv, bv, nullptr, Vb};
        gemm_tf32<0><<<dim3(DD/128, BM/128, 3), 256>>>(a, BM, DD, RR);
    }

    // ---- RoPE ----
    rope_kernel<<<(BB*MM*HH*32)/256, 256>>>(Qb, Kb);

    // ---- flash attention (fp32, rounded output) ----
    cudaFuncSetAttribute(flash_attn, cudaFuncAttributeMaxDynamicSharedMemorySize, FA_SMEM);
    flash_attn<<<dim3(MM/64, HH, BB), 256, FA_SMEM>>>(Qb, Kb, Vb, mask, att);

    // ---- Wo (+bias +residual x) ----
    {
        GemmBatch a{};
        a.op[0] = {att, rw+OFF_WoT, Wo_b, x, xmid};
        gemm_tf32<0><<<dim3(DD/128, BM/128, 1), 256>>>(a, BM, DD, DD);
    }

    // ---- LN2 (rounded) ----
    ln_kernel<<<BM, 256>>>(xmid, ln2w, ln2b, xn2);

    // ---- FFN ----
    {
        GemmBatch a{};
        a.op[0] = {xn2, rw+OFF_U1, nullptr, nullptr, P1};
        gemm_tf32<1><<<dim3(R1/128, BM/128, 1), 256>>>(a, BM, R1, DD);
    }
    {
        GemmBatch a{};
        a.op[0] = {P1, rw+OFF_V1, b1, nullptr, hb};
        gemm_tf32<0><<<dim3((2*FD)/128, BM/128, 1), 256>>>(a, BM, 2*FD, R1);
    }
    geglu_kernel<<<(BM*FD)/256, 256>>>(hb, gb);
    {
        GemmBatch a{};
        a.op[0] = {gb, rw+OFF_U2, nullptr, nullptr, tb};
        gemm_tf32<1><<<dim3(R2/128, BM/128, 1), 256>>>(a, BM, R2, FD);
    }
    {
        GemmBatch a{};
        a.op[0] = {tb, rw+OFF_V2, b2, xmid, out};
        gemm_tf32<0><<<dim3(DD/128, BM/128, 1), 256>>>(a, BM, DD, R2);
    }
}